// round 6
// baseline (speedup 1.0000x reference)
#include <cuda_runtime.h>

// Problem dims
#define BB 16
#define MM 128
#define NHD 256
#define EHD 128
#define HCD (NHD+EHD)    // 384 packed [Hn|He]
#define ROWS (BB*MM)     // 2048

// Scratch (static __device__, no allocations)
__device__ __align__(16) float d_aggE[ROWS*EHD];    // Σ_i A*E  [2048][128]
__device__ __align__(16) float d_sA[ROWS];          // colsum of A
__device__ __align__(16) float d_AX[ROWS*NHD];      // A^T @ X  [2048][256]
__device__ __align__(16) float d_Hc[ROWS*HCD];      // [relu(node)|relu(edge)] [2048][384]
__device__ __align__(16) float d_partX[ROWS*NHD];   // relu(X)@Wu[384:640] partial

#define SMEM_FLOATS (2*16*68)

// ---------------------------------------------------------------------------
// Device GEMM: 64x64 tile, BK=16, 256 threads, 4x4 micro-tile, reg prefetch.
//   TRANSA: A is [k][m];  RELUA: relu on A load;  EPI: relu(acc+srow*bias)
// ---------------------------------------------------------------------------
template<bool TRANSA, bool RELUA, bool EPI>
__device__ __forceinline__
void devgemm(const float* __restrict__ Ab, int lda,
             const float* __restrict__ Bb, int ldb,
             float* __restrict__ Cb, int ldc, int K,
             const float* __restrict__ bias,
             const float* __restrict__ srow,
             int m0, int n0, float* sm) {
    float (*As)[68] = (float(*)[68])sm;
    float (*Bs)[68] = (float(*)[68])(sm + 16*68);

    const int tid = threadIdx.x;
    const int tx = tid & 15;
    const int ty = tid >> 4;

    float acc[4][4] = {};

    float4 ra, rb;
    {
        if (TRANSA) {
            int kk = tid >> 4, c4 = tid & 15;
            ra = *(const float4*)&Ab[(long)kk * lda + m0 + c4 * 4];
        } else {
            int r = tid >> 2, c4 = tid & 3;
            ra = *(const float4*)&Ab[(long)(m0 + r) * lda + c4 * 4];
        }
        int kk = tid >> 4, c4 = tid & 15;
        rb = *(const float4*)&Bb[(long)kk * ldb + n0 + c4 * 4];
    }

    for (int k0 = 0; k0 < K; k0 += 16) {
        if (RELUA) {
            ra.x = fmaxf(ra.x, 0.f); ra.y = fmaxf(ra.y, 0.f);
            ra.z = fmaxf(ra.z, 0.f); ra.w = fmaxf(ra.w, 0.f);
        }
        if (TRANSA) {
            int kk = tid >> 4, c4 = tid & 15;
            *(float4*)&As[kk][c4 * 4] = ra;
        } else {
            int r = tid >> 2, c4 = tid & 3;
            As[c4 * 4 + 0][r] = ra.x;
            As[c4 * 4 + 1][r] = ra.y;
            As[c4 * 4 + 2][r] = ra.z;
            As[c4 * 4 + 3][r] = ra.w;
        }
        {
            int kk = tid >> 4, c4 = tid & 15;
            *(float4*)&Bs[kk][c4 * 4] = rb;
        }
        __syncthreads();

        int kn = k0 + 16;
        if (kn < K) {
            if (TRANSA) {
                int kk = tid >> 4, c4 = tid & 15;
                ra = *(const float4*)&Ab[(long)(kn + kk) * lda + m0 + c4 * 4];
            } else {
                int r = tid >> 2, c4 = tid & 3;
                ra = *(const float4*)&Ab[(long)(m0 + r) * lda + kn + c4 * 4];
            }
            int kk = tid >> 4, c4 = tid & 15;
            rb = *(const float4*)&Bb[(long)(kn + kk) * ldb + n0 + c4 * 4];
        }

        #pragma unroll
        for (int k = 0; k < 16; k++) {
            float4 a4 = *(const float4*)&As[k][ty * 4];
            float4 b4 = *(const float4*)&Bs[k][tx * 4];
            float a[4] = {a4.x, a4.y, a4.z, a4.w};
            float bb[4] = {b4.x, b4.y, b4.z, b4.w};
            #pragma unroll
            for (int i = 0; i < 4; i++)
                #pragma unroll
                for (int jj = 0; jj < 4; jj++)
                    acc[i][jj] = fmaf(a[i], bb[jj], acc[i][jj]);
        }
        __syncthreads();
    }

    float4 bv = make_float4(0.f, 0.f, 0.f, 0.f);
    if (EPI) bv = *(const float4*)&bias[n0 + tx * 4];

    #pragma unroll
    for (int mm = 0; mm < 4; mm++) {
        int r = m0 + ty * 4 + mm;
        float4 v = make_float4(acc[mm][0], acc[mm][1], acc[mm][2], acc[mm][3]);
        if (EPI) {
            float s = srow[r];
            v.x = fmaxf(fmaf(s, bv.x, v.x), 0.f);
            v.y = fmaxf(fmaf(s, bv.y, v.y), 0.f);
            v.z = fmaxf(fmaf(s, bv.z, v.z), 0.f);
            v.w = fmaxf(fmaf(s, bv.w, v.w), 0.f);
        }
        *(float4*)&Cb[(long)r * ldc + n0 + tx * 4] = v;
    }
}

// ---------------------------------------------------------------------------
// Device ereduce: 256 threads, 8 j's per block (one per warp).
// ---------------------------------------------------------------------------
__device__ __forceinline__
void ereduce8(const float* __restrict__ E, const float* __restrict__ A,
              int b, int jg, float* sm) {
    float (*As)[MM] = (float(*)[MM])sm;   // [8][128]
    const int tid = threadIdx.x;
    const int jl  = tid >> 5;
    const int lane = tid & 31;
    const int j0 = jg * 8;

    const float* Ab = A + (long)b * MM * MM;
    for (int idx = tid; idx < 8 * MM; idx += 256) {
        int jj = idx & 7;
        int i  = idx >> 3;
        As[jj][i] = Ab[i * MM + j0 + jj];
    }
    __syncthreads();

    if (tid < 8) {
        float s = 0.f;
        #pragma unroll
        for (int i = 0; i < MM; i++) s += As[tid][i];
        d_sA[b * MM + j0 + tid] = s;
    }

    const int j = j0 + jl;
    const float4* Ep = (const float4*)E + ((long)(b * MM) * MM + j) * (EHD / 4) + lane;
    const long istride = (long)MM * (EHD / 4);

    float4 acc = make_float4(0.f, 0.f, 0.f, 0.f);
    #pragma unroll 16
    for (int i = 0; i < MM; i++) {
        float a  = As[jl][i];
        float4 v = Ep[(long)i * istride];
        acc.x = fmaf(a, v.x, acc.x);
        acc.y = fmaf(a, v.y, acc.y);
        acc.z = fmaf(a, v.z, acc.z);
        acc.w = fmaf(a, v.w, acc.w);
    }
    ((float4*)d_aggE)[(b * MM + j) * (EHD / 4) + lane] = acc;
}

// ---------------------------------------------------------------------------
// Phase 1 (512 blocks): ereduce [0,256) | AX [256,384) | Xpart K=256 [384,512)
// ---------------------------------------------------------------------------
__global__ __launch_bounds__(256, 4)
void phase1_kernel(const float* __restrict__ E, const float* __restrict__ A,
                   const float* __restrict__ X, const float* __restrict__ Wu_w) {
    __shared__ float sm[SMEM_FLOATS];
    const int blk = blockIdx.x;

    if (blk < 256) {
        ereduce8(E, A, blk >> 4, blk & 15, sm);
    } else if (blk < 384) {
        // AX[b] = A[b]^T @ X[b]
        int idx = blk - 256;
        int b = idx >> 3, t = idx & 7;
        int mt = t >> 2, nt = t & 3;
        devgemm<true, false, false>(
            A + (long)b * MM * MM, MM,
            X + (long)b * MM * NHD, NHD,
            d_AX + (long)b * MM * NHD, NHD,
            MM, nullptr, nullptr, mt * 64, nt * 64, sm);
    } else {
        // partX = relu(X) @ Wu_w[384:640, :]   (K=256)
        int idx = blk - 384;
        int mt = idx >> 2, nt = idx & 3;      // 32 x 4
        devgemm<false, true, false>(
            X, NHD,
            Wu_w + (long)384 * NHD, NHD,
            d_partX, NHD,
            NHD, nullptr, nullptr, mt * 64, nt * 64, sm);
    }
}

// ---------------------------------------------------------------------------
// Phase 2 (192 blocks): Hn -> Hc[:,0:256] | He -> Hc[:,256:384]
// ---------------------------------------------------------------------------
__global__ __launch_bounds__(256, 4)
void phase2_kernel(const float* __restrict__ Wv_w, const float* __restrict__ Wv_b,
                   const float* __restrict__ We_w, const float* __restrict__ We_b) {
    __shared__ float sm[SMEM_FLOATS];
    const int blk = blockIdx.x;
    if (blk < 128) {
        int mt = blk >> 2, nt = blk & 3;
        devgemm<false, false, true>(
            d_AX, NHD, Wv_w, NHD, d_Hc, HCD,
            NHD, Wv_b, d_sA, mt * 64, nt * 64, sm);
    } else {
        int idx = blk - 128;
        int mt = idx >> 1, nt = idx & 1;
        devgemm<false, false, true>(
            d_aggE, EHD, We_w, EHD, d_Hc + NHD, HCD,
            EHD, We_b, d_sA, mt * 64, nt * 64, sm);
    }
}

// ---------------------------------------------------------------------------
// Output kernel (256 blocks): out = (Hc @ Wu_w[0:384,:] + partX + Wu_b) * w
// 32x64 tiles, BK=16, 256 threads, 2x4 micro-tile, reg prefetch.
// grid (64 m-tiles, 4 n-tiles)
// ---------------------------------------------------------------------------
__global__ __launch_bounds__(256, 4)
void out_kernel(const float* __restrict__ Wu_w,
                const float* __restrict__ Wu_b,
                const float* __restrict__ w,
                float* __restrict__ out) {
    __shared__ float As[16][36];
    __shared__ float Bs[16][68];

    const int m0 = blockIdx.x * 32;
    const int n0 = blockIdx.y * 64;
    const int tid = threadIdx.x;
    const int tx = tid & 15;
    const int ty = tid >> 4;

    float acc[2][4] = {};

    // A loaders: threads 0..127, r = tid>>2 (32 rows), c4 = tid&3 (4 k-float4)
    float4 ra, rb;
    const bool aload = tid < 128;
    {
        if (aload) {
            int r = tid >> 2, c4 = tid & 3;
            ra = *(const float4*)&d_Hc[(long)(m0 + r) * HCD + c4 * 4];
        }
        int kk = tid >> 4, c4 = tid & 15;
        rb = *(const float4*)&Wu_w[(long)kk * NHD + n0 + c4 * 4];
    }

    for (int k0 = 0; k0 < HCD; k0 += 16) {
        if (aload) {
            int r = tid >> 2, c4 = tid & 3;
            As[c4 * 4 + 0][r] = ra.x;
            As[c4 * 4 + 1][r] = ra.y;
            As[c4 * 4 + 2][r] = ra.z;
            As[c4 * 4 + 3][r] = ra.w;
        }
        {
            int kk = tid >> 4, c4 = tid & 15;
            *(float4*)&Bs[kk][c4 * 4] = rb;
        }
        __syncthreads();

        int kn = k0 + 16;
        if (kn < HCD) {
            if (aload) {
                int r = tid >> 2, c4 = tid & 3;
                ra = *(const float4*)&d_Hc[(long)(m0 + r) * HCD + kn + c4 * 4];
            }
            int kk = tid >> 4, c4 = tid & 15;
            rb = *(const float4*)&Wu_w[(long)(kn + kk) * NHD + n0 + c4 * 4];
        }

        #pragma unroll
        for (int k = 0; k < 16; k++) {
            float a0 = As[k][ty * 2 + 0];
            float a1 = As[k][ty * 2 + 1];
            float4 b4 = *(const float4*)&Bs[k][tx * 4];
            acc[0][0] = fmaf(a0, b4.x, acc[0][0]);
            acc[0][1] = fmaf(a0, b4.y, acc[0][1]);
            acc[0][2] = fmaf(a0, b4.z, acc[0][2]);
            acc[0][3] = fmaf(a0, b4.w, acc[0][3]);
            acc[1][0] = fmaf(a1, b4.x, acc[1][0]);
            acc[1][1] = fmaf(a1, b4.y, acc[1][1]);
            acc[1][2] = fmaf(a1, b4.z, acc[1][2]);
            acc[1][3] = fmaf(a1, b4.w, acc[1][3]);
        }
        __syncthreads();
    }

    float4 bv = *(const float4*)&Wu_b[n0 + tx * 4];
    #pragma unroll
    for (int mm = 0; mm < 2; mm++) {
        int r = m0 + ty * 2 + mm;
        float4 px = *(const float4*)&d_partX[(long)r * NHD + n0 + tx * 4];
        float wv = w[r];
        float4 v;
        v.x = (acc[mm][0] + px.x + bv.x) * wv;
        v.y = (acc[mm][1] + px.y + bv.y) * wv;
        v.z = (acc[mm][2] + px.z + bv.z) * wv;
        v.w = (acc[mm][3] + px.w + bv.w) * wv;
        *(float4*)&out[(long)r * NHD + n0 + tx * 4] = v;
    }
}

// ---------------------------------------------------------------------------
extern "C" void kernel_launch(void* const* d_in, const int* in_sizes, int n_in,
                              void* d_out, int out_size) {
    const float* X    = (const float*)d_in[0];   // [16,128,256]
    const float* E    = (const float*)d_in[1];   // [16,128,128,128]
    const float* A    = (const float*)d_in[2];   // [16,128,128]
    const float* w    = (const float*)d_in[3];   // [16,128,1]
    const float* Wv_w = (const float*)d_in[4];   // [256,256]
    const float* Wv_b = (const float*)d_in[5];   // [256]
    const float* We_w = (const float*)d_in[6];   // [128,128]
    const float* We_b = (const float*)d_in[7];   // [128]
    const float* Wu_w = (const float*)d_in[8];   // [640,256]
    const float* Wu_b = (const float*)d_in[9];   // [256]
    float* out = (float*)d_out;                  // [16,128,256]

    // Phase 1: ereduce + AX + X-partial of final GEMM
    phase1_kernel<<<512, 256>>>(E, A, X, Wu_w);

    // Phase 2: Hn|He packed into d_Hc
    phase2_kernel<<<192, 256>>>(Wv_w, Wv_b, We_w, We_b);

    // Phase 3: fused final GEMM + partial add + bias + w scale
    out_kernel<<<dim3(ROWS / 32, NHD / 64), 256>>>(Wu_w, Wu_b, w, out);
}

// round 7
// speedup vs baseline: 1.0682x; 1.0682x over previous
#include <cuda_runtime.h>

// Problem dims
#define BB 16
#define MM 128
#define NHD 256
#define EHD 128
#define HCD (NHD+EHD)    // 384 packed [Hn|He]
#define ROWS (BB*MM)     // 2048

// Scratch (static __device__, no allocations)
__device__ __align__(16) float d_aggE[ROWS*EHD];    // Σ_i A*E  [2048][128]
__device__ __align__(16) float d_sA[ROWS];          // colsum of A
__device__ __align__(16) float d_AX[ROWS*NHD];      // A^T @ X  [2048][256]
__device__ __align__(16) float d_Hc[ROWS*HCD];      // [relu(node)|relu(edge)] [2048][384]
__device__ __align__(16) float d_partX[ROWS*NHD];   // relu(X)@Wu[384:640] partial

#define SMEM_FLOATS (2*16*68)

// ---------------------------------------------------------------------------
// Device GEMM: 64x64 tile, BK=16, 256 threads, 4x4 micro-tile, reg prefetch.
//   TRANSA: A is [k][m];  RELUA: relu on A load;  EPI: relu(acc+srow*bias)
// ---------------------------------------------------------------------------
template<bool TRANSA, bool RELUA, bool EPI>
__device__ __forceinline__
void devgemm(const float* __restrict__ Ab, int lda,
             const float* __restrict__ Bb, int ldb,
             float* __restrict__ Cb, int ldc, int K,
             const float* __restrict__ bias,
             const float* __restrict__ srow,
             int m0, int n0, float* sm) {
    float (*As)[68] = (float(*)[68])sm;
    float (*Bs)[68] = (float(*)[68])(sm + 16*68);

    const int tid = threadIdx.x;
    const int tx = tid & 15;
    const int ty = tid >> 4;

    float acc[4][4] = {};

    float4 ra, rb;
    {
        if (TRANSA) {
            int kk = tid >> 4, c4 = tid & 15;
            ra = *(const float4*)&Ab[(long)kk * lda + m0 + c4 * 4];
        } else {
            int r = tid >> 2, c4 = tid & 3;
            ra = *(const float4*)&Ab[(long)(m0 + r) * lda + c4 * 4];
        }
        int kk = tid >> 4, c4 = tid & 15;
        rb = *(const float4*)&Bb[(long)kk * ldb + n0 + c4 * 4];
    }

    for (int k0 = 0; k0 < K; k0 += 16) {
        if (RELUA) {
            ra.x = fmaxf(ra.x, 0.f); ra.y = fmaxf(ra.y, 0.f);
            ra.z = fmaxf(ra.z, 0.f); ra.w = fmaxf(ra.w, 0.f);
        }
        if (TRANSA) {
            int kk = tid >> 4, c4 = tid & 15;
            *(float4*)&As[kk][c4 * 4] = ra;
        } else {
            int r = tid >> 2, c4 = tid & 3;
            As[c4 * 4 + 0][r] = ra.x;
            As[c4 * 4 + 1][r] = ra.y;
            As[c4 * 4 + 2][r] = ra.z;
            As[c4 * 4 + 3][r] = ra.w;
        }
        {
            int kk = tid >> 4, c4 = tid & 15;
            *(float4*)&Bs[kk][c4 * 4] = rb;
        }
        __syncthreads();

        int kn = k0 + 16;
        if (kn < K) {
            if (TRANSA) {
                int kk = tid >> 4, c4 = tid & 15;
                ra = *(const float4*)&Ab[(long)(kn + kk) * lda + m0 + c4 * 4];
            } else {
                int r = tid >> 2, c4 = tid & 3;
                ra = *(const float4*)&Ab[(long)(m0 + r) * lda + kn + c4 * 4];
            }
            int kk = tid >> 4, c4 = tid & 15;
            rb = *(const float4*)&Bb[(long)(kn + kk) * ldb + n0 + c4 * 4];
        }

        #pragma unroll
        for (int k = 0; k < 16; k++) {
            float4 a4 = *(const float4*)&As[k][ty * 4];
            float4 b4 = *(const float4*)&Bs[k][tx * 4];
            float a[4] = {a4.x, a4.y, a4.z, a4.w};
            float bb[4] = {b4.x, b4.y, b4.z, b4.w};
            #pragma unroll
            for (int i = 0; i < 4; i++)
                #pragma unroll
                for (int jj = 0; jj < 4; jj++)
                    acc[i][jj] = fmaf(a[i], bb[jj], acc[i][jj]);
        }
        __syncthreads();
    }

    float4 bv = make_float4(0.f, 0.f, 0.f, 0.f);
    if (EPI) bv = *(const float4*)&bias[n0 + tx * 4];

    #pragma unroll
    for (int mm = 0; mm < 4; mm++) {
        int r = m0 + ty * 4 + mm;
        float4 v = make_float4(acc[mm][0], acc[mm][1], acc[mm][2], acc[mm][3]);
        if (EPI) {
            float s = srow[r];
            v.x = fmaxf(fmaf(s, bv.x, v.x), 0.f);
            v.y = fmaxf(fmaf(s, bv.y, v.y), 0.f);
            v.z = fmaxf(fmaf(s, bv.z, v.z), 0.f);
            v.w = fmaxf(fmaf(s, bv.w, v.w), 0.f);
        }
        *(float4*)&Cb[(long)r * ldc + n0 + tx * 4] = v;
    }
}

// ---------------------------------------------------------------------------
// Device ereduce: 256 threads, 8 j's per block (one per warp).
// ---------------------------------------------------------------------------
__device__ __forceinline__
void ereduce8(const float* __restrict__ E, const float* __restrict__ A,
              int b, int jg, float* sm) {
    float (*As)[MM] = (float(*)[MM])sm;   // [8][128]
    const int tid = threadIdx.x;
    const int jl  = tid >> 5;
    const int lane = tid & 31;
    const int j0 = jg * 8;

    const float* Ab = A + (long)b * MM * MM;
    for (int idx = tid; idx < 8 * MM; idx += 256) {
        int jj = idx & 7;
        int i  = idx >> 3;
        As[jj][i] = Ab[i * MM + j0 + jj];
    }
    __syncthreads();

    if (tid < 8) {
        float s = 0.f;
        #pragma unroll
        for (int i = 0; i < MM; i++) s += As[tid][i];
        d_sA[b * MM + j0 + tid] = s;
    }

    const int j = j0 + jl;
    const float4* Ep = (const float4*)E + ((long)(b * MM) * MM + j) * (EHD / 4) + lane;
    const long istride = (long)MM * (EHD / 4);

    float4 acc = make_float4(0.f, 0.f, 0.f, 0.f);
    #pragma unroll 8
    for (int i = 0; i < MM; i++) {
        float a  = As[jl][i];
        float4 v = Ep[(long)i * istride];
        acc.x = fmaf(a, v.x, acc.x);
        acc.y = fmaf(a, v.y, acc.y);
        acc.z = fmaf(a, v.z, acc.z);
        acc.w = fmaf(a, v.w, acc.w);
    }
    ((float4*)d_aggE)[(b * MM + j) * (EHD / 4) + lane] = acc;
}

// ---------------------------------------------------------------------------
// Phase 1 (512 blocks): ereduce [0,256) | AX [256,384) | Xpart K=256 [384,512)
// ---------------------------------------------------------------------------
__global__ __launch_bounds__(256, 4)
void phase1_kernel(const float* __restrict__ E, const float* __restrict__ A,
                   const float* __restrict__ X, const float* __restrict__ Wu_w) {
    __shared__ float sm[SMEM_FLOATS];
    const int blk = blockIdx.x;

    if (blk < 256) {
        ereduce8(E, A, blk >> 4, blk & 15, sm);
    } else if (blk < 384) {
        // AX[b] = A[b]^T @ X[b]
        int idx = blk - 256;
        int b = idx >> 3, t = idx & 7;
        int mt = t >> 2, nt = t & 3;
        devgemm<true, false, false>(
            A + (long)b * MM * MM, MM,
            X + (long)b * MM * NHD, NHD,
            d_AX + (long)b * MM * NHD, NHD,
            MM, nullptr, nullptr, mt * 64, nt * 64, sm);
    } else {
        // partX = relu(X) @ Wu_w[384:640, :]   (K=256)
        int idx = blk - 384;
        int mt = idx >> 2, nt = idx & 3;      // 32 x 4
        devgemm<false, true, false>(
            X, NHD,
            Wu_w + (long)384 * NHD, NHD,
            d_partX, NHD,
            NHD, nullptr, nullptr, mt * 64, nt * 64, sm);
    }
}

// ---------------------------------------------------------------------------
// Phase 2 (192 blocks): Hn -> Hc[:,0:256] | He -> Hc[:,256:384]
// ---------------------------------------------------------------------------
__global__ __launch_bounds__(256, 4)
void phase2_kernel(const float* __restrict__ Wv_w, const float* __restrict__ Wv_b,
                   const float* __restrict__ We_w, const float* __restrict__ We_b) {
    __shared__ float sm[SMEM_FLOATS];
    const int blk = blockIdx.x;
    if (blk < 128) {
        int mt = blk >> 2, nt = blk & 3;
        devgemm<false, false, true>(
            d_AX, NHD, Wv_w, NHD, d_Hc, HCD,
            NHD, Wv_b, d_sA, mt * 64, nt * 64, sm);
    } else {
        int idx = blk - 128;
        int mt = idx >> 1, nt = idx & 1;
        devgemm<false, false, true>(
            d_aggE, EHD, We_w, EHD, d_Hc + NHD, HCD,
            EHD, We_b, d_sA, mt * 64, nt * 64, sm);
    }
}

// ---------------------------------------------------------------------------
// Output kernel (128 blocks): out = (Hc @ Wu_w[0:384,:] + partX + Wu_b) * w
// 64x64 tiles, BK=16, 256 threads, 4x4 micro-tile, reg prefetch, K=384.
// grid (32 m-tiles, 4 n-tiles)
// ---------------------------------------------------------------------------
__global__ __launch_bounds__(256, 4)
void out_kernel(const float* __restrict__ Wu_w,
                const float* __restrict__ Wu_b,
                const float* __restrict__ w,
                float* __restrict__ out) {
    __shared__ float As[16][68];
    __shared__ float Bs[16][68];

    const int m0 = blockIdx.x * 64;
    const int n0 = blockIdx.y * 64;
    const int tid = threadIdx.x;
    const int tx = tid & 15;
    const int ty = tid >> 4;

    float acc[4][4] = {};

    float4 ra, rb;
    {
        int r = tid >> 2, c4 = tid & 3;
        ra = *(const float4*)&d_Hc[(long)(m0 + r) * HCD + c4 * 4];
        int kk = tid >> 4, c4b = tid & 15;
        rb = *(const float4*)&Wu_w[(long)kk * NHD + n0 + c4b * 4];
    }

    for (int k0 = 0; k0 < HCD; k0 += 16) {
        {
            int r = tid >> 2, c4 = tid & 3;
            As[c4 * 4 + 0][r] = ra.x;
            As[c4 * 4 + 1][r] = ra.y;
            As[c4 * 4 + 2][r] = ra.z;
            As[c4 * 4 + 3][r] = ra.w;
            int kk = tid >> 4, c4b = tid & 15;
            *(float4*)&Bs[kk][c4b * 4] = rb;
        }
        __syncthreads();

        int kn = k0 + 16;
        if (kn < HCD) {
            int r = tid >> 2, c4 = tid & 3;
            ra = *(const float4*)&d_Hc[(long)(m0 + r) * HCD + kn + c4 * 4];
            int kk = tid >> 4, c4b = tid & 15;
            rb = *(const float4*)&Wu_w[(long)(kn + kk) * NHD + n0 + c4b * 4];
        }

        #pragma unroll
        for (int k = 0; k < 16; k++) {
            float4 a4 = *(const float4*)&As[k][ty * 4];
            float4 b4 = *(const float4*)&Bs[k][tx * 4];
            float a[4] = {a4.x, a4.y, a4.z, a4.w};
            float bb[4] = {b4.x, b4.y, b4.z, b4.w};
            #pragma unroll
            for (int i = 0; i < 4; i++)
                #pragma unroll
                for (int jj = 0; jj < 4; jj++)
                    acc[i][jj] = fmaf(a[i], bb[jj], acc[i][jj]);
        }
        __syncthreads();
    }

    float4 bv = *(const float4*)&Wu_b[n0 + tx * 4];
    #pragma unroll
    for (int mm = 0; mm < 4; mm++) {
        int r = m0 + ty * 4 + mm;
        float4 px = *(const float4*)&d_partX[(long)r * NHD + n0 + tx * 4];
        float wv = w[r];
        float4 v;
        v.x = (acc[mm][0] + px.x + bv.x) * wv;
        v.y = (acc[mm][1] + px.y + bv.y) * wv;
        v.z = (acc[mm][2] + px.z + bv.z) * wv;
        v.w = (acc[mm][3] + px.w + bv.w) * wv;
        *(float4*)&out[(long)r * NHD + n0 + tx * 4] = v;
    }
}

// ---------------------------------------------------------------------------
extern "C" void kernel_launch(void* const* d_in, const int* in_sizes, int n_in,
                              void* d_out, int out_size) {
    const float* X    = (const float*)d_in[0];   // [16,128,256]
    const float* E    = (const float*)d_in[1];   // [16,128,128,128]
    const float* A    = (const float*)d_in[2];   // [16,128,128]
    const float* w    = (const float*)d_in[3];   // [16,128,1]
    const float* Wv_w = (const float*)d_in[4];   // [256,256]
    const float* Wv_b = (const float*)d_in[5];   // [256]
    const float* We_w = (const float*)d_in[6];   // [128,128]
    const float* We_b = (const float*)d_in[7];   // [128]
    const float* Wu_w = (const float*)d_in[8];   // [640,256]
    const float* Wu_b = (const float*)d_in[9];   // [256]
    float* out = (float*)d_out;                  // [16,128,256]

    // Phase 1: ereduce + AX + X-partial of final GEMM
    phase1_kernel<<<512, 256>>>(E, A, X, Wu_w);

    // Phase 2: Hn|He packed into d_Hc
    phase2_kernel<<<192, 256>>>(Wv_w, Wv_b, We_w, We_b);

    // Phase 3: fused final GEMM + partial add + bias + w scale
    out_kernel<<<dim3(ROWS / 64, NHD / 64), 256>>>(Wu_w, Wu_b, w, out);
}

// round 8
// speedup vs baseline: 1.1411x; 1.0683x over previous
#include <cuda_runtime.h>

// Problem dims
#define BB 16
#define MM 128
#define NHD 256
#define EHD 128
#define HCD (NHD+EHD)    // 384 packed [Hn|He]
#define ROWS (BB*MM)     // 2048

typedef unsigned long long u64;

// Scratch (static __device__, no allocations)
__device__ __align__(16) float d_aggE[ROWS*EHD];    // Σ_i A*E  [2048][128]
__device__ __align__(16) float d_sA[ROWS];          // colsum of A
__device__ __align__(16) float d_AX[ROWS*NHD];      // A^T @ X  [2048][256]
__device__ __align__(16) float d_Hc[ROWS*HCD];      // [relu(node)|relu(edge)] [2048][384]
__device__ __align__(16) float d_partX[ROWS*NHD];   // relu(X)@Wu[384:640] partial

#define SMEM_FLOATS (2*16*68)

// ---- packed f32x2 helpers (Blackwell packed fp32 pipe, PTX-only) ----------
__device__ __forceinline__ u64 bcast2(float v) {
    u64 r; asm("mov.b64 %0, {%1, %1};" : "=l"(r) : "f"(v)); return r;
}
__device__ __forceinline__ void fmax2(u64 &d, u64 a, u64 b) {
    asm("fma.rn.f32x2 %0, %1, %2, %0;" : "+l"(d) : "l"(a), "l"(b));
}
__device__ __forceinline__ void unpack2(u64 v, float &lo, float &hi) {
    asm("mov.b64 {%0, %1}, %2;" : "=f"(lo), "=f"(hi) : "l"(v));
}

// ---------------------------------------------------------------------------
// Device GEMM: 64x64 tile, BK=16, 256 threads, 4x4 micro-tile (f32x2 packed),
// register-prefetch double buffering.
//   TRANSA: A is [k][m];  RELUA: relu on A load;  EPI: relu(acc+srow*bias)
// ---------------------------------------------------------------------------
template<bool TRANSA, bool RELUA, bool EPI>
__device__ __forceinline__
void devgemm(const float* __restrict__ Ab, int lda,
             const float* __restrict__ Bb, int ldb,
             float* __restrict__ Cb, int ldc, int K,
             const float* __restrict__ bias,
             const float* __restrict__ srow,
             int m0, int n0, float* sm) {
    float (*As)[68] = (float(*)[68])sm;
    float (*Bs)[68] = (float(*)[68])(sm + 16*68);

    const int tid = threadIdx.x;
    const int tx = tid & 15;
    const int ty = tid >> 4;

    u64 acc2[4][2] = {};   // [m][n-pair], each = 2 packed fp32

    float4 ra, rb;
    {
        if (TRANSA) {
            int kk = tid >> 4, c4 = tid & 15;
            ra = *(const float4*)&Ab[(long)kk * lda + m0 + c4 * 4];
        } else {
            int r = tid >> 2, c4 = tid & 3;
            ra = *(const float4*)&Ab[(long)(m0 + r) * lda + c4 * 4];
        }
        int kk = tid >> 4, c4 = tid & 15;
        rb = *(const float4*)&Bb[(long)kk * ldb + n0 + c4 * 4];
    }

    for (int k0 = 0; k0 < K; k0 += 16) {
        if (RELUA) {
            ra.x = fmaxf(ra.x, 0.f); ra.y = fmaxf(ra.y, 0.f);
            ra.z = fmaxf(ra.z, 0.f); ra.w = fmaxf(ra.w, 0.f);
        }
        if (TRANSA) {
            int kk = tid >> 4, c4 = tid & 15;
            *(float4*)&As[kk][c4 * 4] = ra;
        } else {
            int r = tid >> 2, c4 = tid & 3;
            As[c4 * 4 + 0][r] = ra.x;
            As[c4 * 4 + 1][r] = ra.y;
            As[c4 * 4 + 2][r] = ra.z;
            As[c4 * 4 + 3][r] = ra.w;
        }
        {
            int kk = tid >> 4, c4 = tid & 15;
            *(float4*)&Bs[kk][c4 * 4] = rb;
        }
        __syncthreads();

        int kn = k0 + 16;
        if (kn < K) {
            if (TRANSA) {
                int kk = tid >> 4, c4 = tid & 15;
                ra = *(const float4*)&Ab[(long)(kn + kk) * lda + m0 + c4 * 4];
            } else {
                int r = tid >> 2, c4 = tid & 3;
                ra = *(const float4*)&Ab[(long)(m0 + r) * lda + kn + c4 * 4];
            }
            int kk = tid >> 4, c4 = tid & 15;
            rb = *(const float4*)&Bb[(long)(kn + kk) * ldb + n0 + c4 * 4];
        }

        #pragma unroll
        for (int k = 0; k < 16; k++) {
            float4 a4 = *(const float4*)&As[k][ty * 4];
            ulonglong2 bv = *(const ulonglong2*)&Bs[k][tx * 4];  // 4 floats as 2 packs
            u64 a0 = bcast2(a4.x), a1 = bcast2(a4.y);
            u64 a2 = bcast2(a4.z), a3 = bcast2(a4.w);
            fmax2(acc2[0][0], a0, bv.x); fmax2(acc2[0][1], a0, bv.y);
            fmax2(acc2[1][0], a1, bv.x); fmax2(acc2[1][1], a1, bv.y);
            fmax2(acc2[2][0], a2, bv.x); fmax2(acc2[2][1], a2, bv.y);
            fmax2(acc2[3][0], a3, bv.x); fmax2(acc2[3][1], a3, bv.y);
        }
        __syncthreads();
    }

    float4 bvv = make_float4(0.f, 0.f, 0.f, 0.f);
    if (EPI) bvv = *(const float4*)&bias[n0 + tx * 4];

    #pragma unroll
    for (int mm = 0; mm < 4; mm++) {
        int r = m0 + ty * 4 + mm;
        float4 v;
        unpack2(acc2[mm][0], v.x, v.y);
        unpack2(acc2[mm][1], v.z, v.w);
        if (EPI) {
            float s = srow[r];
            v.x = fmaxf(fmaf(s, bvv.x, v.x), 0.f);
            v.y = fmaxf(fmaf(s, bvv.y, v.y), 0.f);
            v.z = fmaxf(fmaf(s, bvv.z, v.z), 0.f);
            v.w = fmaxf(fmaf(s, bvv.w, v.w), 0.f);
        }
        *(float4*)&Cb[(long)r * ldc + n0 + tx * 4] = v;
    }
}

// ---------------------------------------------------------------------------
// Device ereduce: 256 threads, 8 j's per block (one per warp).
// ---------------------------------------------------------------------------
__device__ __forceinline__
void ereduce8(const float* __restrict__ E, const float* __restrict__ A,
              int b, int jg, float* sm) {
    float (*As)[MM] = (float(*)[MM])sm;   // [8][128]
    const int tid = threadIdx.x;
    const int jl  = tid >> 5;
    const int lane = tid & 31;
    const int j0 = jg * 8;

    const float* Ab = A + (long)b * MM * MM;
    for (int idx = tid; idx < 8 * MM; idx += 256) {
        int jj = idx & 7;
        int i  = idx >> 3;
        As[jj][i] = Ab[i * MM + j0 + jj];
    }
    __syncthreads();

    if (tid < 8) {
        float s = 0.f;
        #pragma unroll
        for (int i = 0; i < MM; i++) s += As[tid][i];
        d_sA[b * MM + j0 + tid] = s;
    }

    const int j = j0 + jl;
    const float4* Ep = (const float4*)E + ((long)(b * MM) * MM + j) * (EHD / 4) + lane;
    const long istride = (long)MM * (EHD / 4);

    float4 acc = make_float4(0.f, 0.f, 0.f, 0.f);
    #pragma unroll 8
    for (int i = 0; i < MM; i++) {
        float a  = As[jl][i];
        float4 v = Ep[(long)i * istride];
        acc.x = fmaf(a, v.x, acc.x);
        acc.y = fmaf(a, v.y, acc.y);
        acc.z = fmaf(a, v.z, acc.z);
        acc.w = fmaf(a, v.w, acc.w);
    }
    ((float4*)d_aggE)[(b * MM + j) * (EHD / 4) + lane] = acc;
}

// ---------------------------------------------------------------------------
// Phase 1 (512 blocks): ereduce [0,256) | AX [256,384) | Xpart K=256 [384,512)
// ---------------------------------------------------------------------------
__global__ __launch_bounds__(256, 4)
void phase1_kernel(const float* __restrict__ E, const float* __restrict__ A,
                   const float* __restrict__ X, const float* __restrict__ Wu_w) {
    __shared__ float sm[SMEM_FLOATS];
    const int blk = blockIdx.x;

    if (blk < 256) {
        ereduce8(E, A, blk >> 4, blk & 15, sm);
    } else if (blk < 384) {
        // AX[b] = A[b]^T @ X[b]
        int idx = blk - 256;
        int b = idx >> 3, t = idx & 7;
        int mt = t >> 2, nt = t & 3;
        devgemm<true, false, false>(
            A + (long)b * MM * MM, MM,
            X + (long)b * MM * NHD, NHD,
            d_AX + (long)b * MM * NHD, NHD,
            MM, nullptr, nullptr, mt * 64, nt * 64, sm);
    } else {
        // partX = relu(X) @ Wu_w[384:640, :]   (K=256)
        int idx = blk - 384;
        int mt = idx >> 2, nt = idx & 3;      // 32 x 4
        devgemm<false, true, false>(
            X, NHD,
            Wu_w + (long)384 * NHD, NHD,
            d_partX, NHD,
            NHD, nullptr, nullptr, mt * 64, nt * 64, sm);
    }
}

// ---------------------------------------------------------------------------
// Phase 2 (192 blocks): Hn -> Hc[:,0:256] | He -> Hc[:,256:384]
// ---------------------------------------------------------------------------
__global__ __launch_bounds__(256, 4)
void phase2_kernel(const float* __restrict__ Wv_w, const float* __restrict__ Wv_b,
                   const float* __restrict__ We_w, const float* __restrict__ We_b) {
    __shared__ float sm[SMEM_FLOATS];
    const int blk = blockIdx.x;
    if (blk < 128) {
        int mt = blk >> 2, nt = blk & 3;
        devgemm<false, false, true>(
            d_AX, NHD, Wv_w, NHD, d_Hc, HCD,
            NHD, Wv_b, d_sA, mt * 64, nt * 64, sm);
    } else {
        int idx = blk - 128;
        int mt = idx >> 1, nt = idx & 1;
        devgemm<false, false, true>(
            d_aggE, EHD, We_w, EHD, d_Hc + NHD, HCD,
            EHD, We_b, d_sA, mt * 64, nt * 64, sm);
    }
}

// ---------------------------------------------------------------------------
// Output kernel (128 blocks): out = (Hc @ Wu_w[0:384,:] + partX + Wu_b) * w
// 64x64 tiles, BK=16, 256 threads, 4x4 (f32x2) micro-tile, K=384.
// ---------------------------------------------------------------------------
__global__ __launch_bounds__(256, 4)
void out_kernel(const float* __restrict__ Wu_w,
                const float* __restrict__ Wu_b,
                const float* __restrict__ w,
                float* __restrict__ out) {
    __shared__ float As[16][68];
    __shared__ float Bs[16][68];

    const int m0 = blockIdx.x * 64;
    const int n0 = blockIdx.y * 64;
    const int tid = threadIdx.x;
    const int tx = tid & 15;
    const int ty = tid >> 4;

    u64 acc2[4][2] = {};

    float4 ra, rb;
    {
        int r = tid >> 2, c4 = tid & 3;
        ra = *(const float4*)&d_Hc[(long)(m0 + r) * HCD + c4 * 4];
        int kk = tid >> 4, c4b = tid & 15;
        rb = *(const float4*)&Wu_w[(long)kk * NHD + n0 + c4b * 4];
    }

    for (int k0 = 0; k0 < HCD; k0 += 16) {
        {
            int r = tid >> 2, c4 = tid & 3;
            As[c4 * 4 + 0][r] = ra.x;
            As[c4 * 4 + 1][r] = ra.y;
            As[c4 * 4 + 2][r] = ra.z;
            As[c4 * 4 + 3][r] = ra.w;
            int kk = tid >> 4, c4b = tid & 15;
            *(float4*)&Bs[kk][c4b * 4] = rb;
        }
        __syncthreads();

        int kn = k0 + 16;
        if (kn < HCD) {
            int r = tid >> 2, c4 = tid & 3;
            ra = *(const float4*)&d_Hc[(long)(m0 + r) * HCD + kn + c4 * 4];
            int kk = tid >> 4, c4b = tid & 15;
            rb = *(const float4*)&Wu_w[(long)(kn + kk) * NHD + n0 + c4b * 4];
        }

        #pragma unroll
        for (int k = 0; k < 16; k++) {
            float4 a4 = *(const float4*)&As[k][ty * 4];
            ulonglong2 bv = *(const ulonglong2*)&Bs[k][tx * 4];
            u64 a0 = bcast2(a4.x), a1 = bcast2(a4.y);
            u64 a2 = bcast2(a4.z), a3 = bcast2(a4.w);
            fmax2(acc2[0][0], a0, bv.x); fmax2(acc2[0][1], a0, bv.y);
            fmax2(acc2[1][0], a1, bv.x); fmax2(acc2[1][1], a1, bv.y);
            fmax2(acc2[2][0], a2, bv.x); fmax2(acc2[2][1], a2, bv.y);
            fmax2(acc2[3][0], a3, bv.x); fmax2(acc2[3][1], a3, bv.y);
        }
        __syncthreads();
    }

    float4 bvv = *(const float4*)&Wu_b[n0 + tx * 4];
    #pragma unroll
    for (int mm = 0; mm < 4; mm++) {
        int r = m0 + ty * 4 + mm;
        float4 px = *(const float4*)&d_partX[(long)r * NHD + n0 + tx * 4];
        float wv = w[r];
        float4 v;
        unpack2(acc2[mm][0], v.x, v.y);
        unpack2(acc2[mm][1], v.z, v.w);
        v.x = (v.x + px.x + bvv.x) * wv;
        v.y = (v.y + px.y + bvv.y) * wv;
        v.z = (v.z + px.z + bvv.z) * wv;
        v.w = (v.w + px.w + bvv.w) * wv;
        *(float4*)&out[(long)r * NHD + n0 + tx * 4] = v;
    }
}

// ---------------------------------------------------------------------------
extern "C" void kernel_launch(void* const* d_in, const int* in_sizes, int n_in,
                              void* d_out, int out_size) {
    const float* X    = (const float*)d_in[0];   // [16,128,256]
    const float* E    = (const float*)d_in[1];   // [16,128,128,128]
    const float* A    = (const float*)d_in[2];   // [16,128,128]
    const float* w    = (const float*)d_in[3];   // [16,128,1]
    const float* Wv_w = (const float*)d_in[4];   // [256,256]
    const float* Wv_b = (const float*)d_in[5];   // [256]
    const float* We_w = (const float*)d_in[6];   // [128,128]
    const float* We_b = (const float*)d_in[7];   // [128]
    const float* Wu_w = (const float*)d_in[8];   // [640,256]
    const float* Wu_b = (const float*)d_in[9];   // [256]
    float* out = (float*)d_out;                  // [16,128,256]

    // Phase 1: ereduce + AX + X-partial of final GEMM
    phase1_kernel<<<512, 256>>>(E, A, X, Wu_w);

    // Phase 2: Hn|He packed into d_Hc
    phase2_kernel<<<192, 256>>>(Wv_w, Wv_b, We_w, We_b);

    // Phase 3: fused final GEMM + partial add + bias + w scale
    out_kernel<<<dim3(ROWS / 64, NHD / 64), 256>>>(Wu_w, Wu_b, w, out);
}